// round 13
// baseline (speedup 1.0000x reference)
#include <cuda_runtime.h>

#define B_    256
#define T_    1024
#define NUM_  126
#define L_    128

__device__ int d_perm[B_];

// Rank-sort sequences by length (descending), deterministic, O(n^2) with n=256.
__global__ void crf_sort_kernel(const int* __restrict__ lens){
    __shared__ int sl[B_];
    int i = threadIdx.x;
    sl[i] = lens[i];
    __syncthreads();
    int v = sl[i];
    int r = 0;
    #pragma unroll 8
    for (int j = 0; j < B_; j++){
        int w = sl[j];
        r += (int)((w > v) | ((w == v) & (j < i)));
    }
    d_perm[r] = i;
}

__device__ __forceinline__ void ffma2(unsigned long long &d, unsigned long long a, unsigned long long b){
    asm volatile("fma.rn.f32x2 %0, %1, %2, %0;" : "+l"(d) : "l"(a), "l"(b));
}
__device__ __forceinline__ unsigned long long fadd2(unsigned long long a, unsigned long long b){
    unsigned long long d;
    asm volatile("add.rn.f32x2 %0, %1, %2;" : "=l"(d) : "l"(a), "l"(b));
    return d;
}
__device__ __forceinline__ float sum2(unsigned long long s2){
    return __uint_as_float((unsigned)(s2 & 0xffffffffull)) +
           __uint_as_float((unsigned)(s2 >> 32));
}
// Warp max of a NON-NEGATIVE float (bits are s32-monotonic).
__device__ __forceinline__ float redux_max_pos(float v){
    int r;
    asm volatile("redux.sync.max.s32 %0, %1, 0xffffffff;" : "=r"(r) : "r"(__float_as_int(v)));
    return __int_as_float(r);
}
__device__ __forceinline__ float blockmax4(const float* red){
    float4 rv = *(const float4*)red;
    return fmaxf(fmaxf(rv.x, rv.y), fmaxf(rv.z, rv.w));
}

// Single 128-dot: pure broadcast LDS, E in 64 packed f32x2 regs.
__device__ __forceinline__ float dot128(const float* __restrict__ p, const unsigned long long* __restrict__ E){
    const ulonglong2* pd = (const ulonglong2*)p;
    unsigned long long a0 = 0ull, a1 = 0ull, a2 = 0ull, a3 = 0ull;
    #pragma unroll
    for (int i = 0; i < 32; i += 2){
        ulonglong2 q0 = pd[i];
        ulonglong2 q1 = pd[i + 1];
        ffma2(a0, E[2*i + 0], q0.x);
        ffma2(a1, E[2*i + 1], q0.y);
        ffma2(a2, E[2*i + 2], q1.x);
        ffma2(a3, E[2*i + 3], q1.y);
    }
    return sum2(fadd2(fadd2(a0, a1), fadd2(a2, a3)));
}

// Dual 128-dot over two p vectors sharing one E set: interleaved for ILP.
__device__ __forceinline__ void dot128x2(const float* __restrict__ pA, const float* __restrict__ pB,
                                         const unsigned long long* __restrict__ E,
                                         float &sA, float &sB){
    const ulonglong2* a = (const ulonglong2*)pA;
    const ulonglong2* b = (const ulonglong2*)pB;
    unsigned long long A0=0ull,A1=0ull,A2=0ull,A3=0ull,B0=0ull,B1=0ull,B2=0ull,B3=0ull;
    #pragma unroll
    for (int i = 0; i < 32; i += 2){
        ulonglong2 qa0 = a[i], qb0 = b[i], qa1 = a[i+1], qb1 = b[i+1];
        ffma2(A0, E[2*i + 0], qa0.x);  ffma2(B0, E[2*i + 0], qb0.x);
        ffma2(A1, E[2*i + 1], qa0.y);  ffma2(B1, E[2*i + 1], qb0.y);
        ffma2(A2, E[2*i + 2], qa1.x);  ffma2(B2, E[2*i + 2], qb1.x);
        ffma2(A3, E[2*i + 3], qa1.y);  ffma2(B3, E[2*i + 3], qb1.y);
    }
    sA = sum2(fadd2(fadd2(A0, A1), fadd2(A2, A3)));
    sB = sum2(fadd2(fadd2(B0, B1), fadd2(B2, B3)));
}

#define GBAR(id) asm volatile("bar.sync %0, 128;" :: "r"(id) : "memory")

__global__ void __launch_bounds__(256, 1)
crf_main_kernel(const float* __restrict__ logits,
                const int*   __restrict__ labels,
                const int*   __restrict__ lens,
                const float* __restrict__ trans,
                float*       __restrict__ out)
{
    __shared__ __align__(16) float pf [2][2][L_];    // fwd  [seq][parity][j]
    __shared__ __align__(16) float pbw[2][2][L_];    // bwd  [seq][parity][j]
    __shared__ __align__(16) float redf[2][2][4];    // fwd maxima [seq][parity][warp]
    __shared__ __align__(16) float redb[2][2][4];
    __shared__ float scal[2][2];                     // [seq][dir]
    __shared__ float redS[2][4], redG[2][4];

    const int tid   = threadIdx.x;
    const int grp   = tid >> 7;        // 0 = forward group, 1 = backward group
    const int jt    = tid & 127;
    const int lane  = tid & 31;
    const int wp    = jt >> 5;         // warp in group
    const int barid = 1 + grp;
    const int bid   = (int)blockIdx.x;

    const int seqA = d_perm[2*bid], seqB = d_perm[2*bid + 1];
    const int lA = lens[seqA], lB = lens[seqB];
    const int mA = lA >> 1, KA = lA - mA;
    const int mB = lB >> 1, KB = lB - mB;

    // ---- E regs: fwd = exp(Tr) row jt; bwd = exp(Tr) column jt ----
    unsigned long long E[64];
    #pragma unroll
    for (int q = 0; q < 64; q++){
        float e0, e1;
        if (grp == 0){
            e0 = expf(trans[jt * L_ + 2*q]);
            e1 = expf(trans[jt * L_ + 2*q + 1]);
        } else {
            e0 = expf(trans[(2*q    ) * L_ + jt]);
            e1 = expf(trans[(2*q + 1) * L_ + jt]);
        }
        E[q] = (unsigned long long)__float_as_uint(e0)
             | ((unsigned long long)__float_as_uint(e1) << 32);
    }

    const float* lgpA = logits + (size_t)seqA * T_ * NUM_;
    const float* lgpB = logits + (size_t)seqB * T_ * NUM_;

    // ---- gold score partial: group g handles seq g ----
    float gpart = 0.f;
    {
        const int   seqX = grp ? seqB : seqA;
        const int   lX   = grp ? lB   : lA;
        const float* lgX = grp ? lgpB : lgpA;
        const int*  lab  = labels + seqX * T_;
        for (int t = jt; t < lX; t += 128){
            int l1 = lab[t];
            gpart += lgX[(size_t)t * NUM_ + l1];
            int l0 = (t == 0) ? (L_ - 2) : lab[t - 1];
            gpart += trans[l1 * L_ + l0];
        }
        if (jt == 0) gpart += trans[(L_ - 1) * L_ + lab[lX - 1]];
    }

    const bool ok = (jt < NUM_);
    float cA = 0.f, rA = 1.f, MA = 1.f;
    float cB = 0.f, rB = 1.f, MB = 1.f;

    if (grp == 0){
        // ======================= FORWARD: a <- u_t * (E a) =======================
        pf[0][0][jt] = (jt == (L_ - 2)) ? 1.f : 0.f;
        pf[1][0][jt] = (jt == (L_ - 2)) ? 1.f : 0.f;
        GBAR(1);
        float uA[4], uB[4];
        #pragma unroll
        for (int k = 0; k < 4; k++){
            uA[k] = ok ? __expf(__ldg(lgpA + (size_t)k * NUM_ + jt)) : 0.f;
            uB[k] = ok ? __expf(__ldg(lgpB + (size_t)k * NUM_ + jt)) : 0.f;
        }
        const int mMax = (mA > mB) ? mA : mB;
        int t0 = 0;
        while (t0 + 4 <= mMax){
            float nA[4], nB[4];
            #pragma unroll
            for (int k = 0; k < 4; k++){
                int tp = t0 + 4 + k;
                nA[k] = (ok && tp < T_) ? __ldg(lgpA + (size_t)tp * NUM_ + jt) : -1.0e30f;
                nB[k] = (ok && tp < T_) ? __ldg(lgpB + (size_t)tp * NUM_ + jt) : -1.0e30f;
            }
            #pragma unroll
            for (int k = 0; k < 4; k++){
                const int t = t0 + k;
                const bool aAct = (t < mA), bAct = (t < mB);     // uniform in group
                if (aAct & bAct){
                    float sA, sB;
                    dot128x2(pf[0][t & 1], pf[1][t & 1], E, sA, sB);
                    float vA = sA * uA[k] * rA;
                    float vB = sB * uB[k] * rB;
                    float MwA = redux_max_pos(vA);
                    float MwB = redux_max_pos(vB);
                    if (lane == 0){ redf[0][t & 1][wp] = MwA; redf[1][t & 1][wp] = MwB; }
                    pf[0][(t & 1) ^ 1][jt] = vA;
                    pf[1][(t & 1) ^ 1][jt] = vB;
                } else if (aAct){
                    float vA = dot128(pf[0][t & 1], E) * uA[k] * rA;
                    float MwA = redux_max_pos(vA);
                    if (lane == 0) redf[0][t & 1][wp] = MwA;
                    pf[0][(t & 1) ^ 1][jt] = vA;
                } else if (bAct){
                    float vB = dot128(pf[1][t & 1], E) * uB[k] * rB;
                    float MwB = redux_max_pos(vB);
                    if (lane == 0) redf[1][t & 1][wp] = MwB;
                    pf[1][(t & 1) ^ 1][jt] = vB;
                }
                GBAR(1);
                if (aAct){ MA = blockmax4(redf[0][t & 1]); rA = __fdividef(1.f, MA); cA += __logf(MA); }
                if (bAct){ MB = blockmax4(redf[1][t & 1]); rB = __fdividef(1.f, MB); cB += __logf(MB); }
            }
            #pragma unroll
            for (int k = 0; k < 4; k++){ uA[k] = __expf(nA[k]); uB[k] = __expf(nB[k]); }
            t0 += 4;
        }
        #pragma unroll
        for (int k = 0; k < 3; k++){
            const int t = t0 + k;
            if (t < mMax){
                const bool aAct = (t < mA), bAct = (t < mB);
                if (aAct){
                    float vA = dot128(pf[0][t & 1], E) * uA[k] * rA;
                    float MwA = redux_max_pos(vA);
                    if (lane == 0) redf[0][t & 1][wp] = MwA;
                    pf[0][(t & 1) ^ 1][jt] = vA;
                }
                if (bAct){
                    float vB = dot128(pf[1][t & 1], E) * uB[k] * rB;
                    float MwB = redux_max_pos(vB);
                    if (lane == 0) redf[1][t & 1][wp] = MwB;
                    pf[1][(t & 1) ^ 1][jt] = vB;
                }
                GBAR(1);
                if (aAct){ MA = blockmax4(redf[0][t & 1]); rA = __fdividef(1.f, MA); cA += __logf(MA); }
                if (bAct){ MB = blockmax4(redf[1][t & 1]); rB = __fdividef(1.f, MB); cB += __logf(MB); }
            }
        }
        if (jt == 0){ scal[0][0] = cA - __logf(MA); scal[1][0] = cB - __logf(MB); }
    } else {
        // ======================= BACKWARD: b <- E^T (u_t * b) =======================
        float wj  = __expf(trans[(L_ - 1) * L_ + jt]);
        float u0A = ok ? __expf(__ldg(lgpA + (size_t)(lA - 1) * NUM_ + jt)) : 0.f;
        float u0B = ok ? __expf(__ldg(lgpB + (size_t)(lB - 1) * NUM_ + jt)) : 0.f;
        float vA0 = u0A * wj, vB0 = u0B * wj;
        float MwA0 = redux_max_pos(vA0), MwB0 = redux_max_pos(vB0);
        if (lane == 0){ redb[0][0][wp] = MwA0; redb[1][0][wp] = MwB0; }
        pbw[0][0][jt] = vA0;
        pbw[1][0][jt] = vB0;
        GBAR(2);
        MA = blockmax4(redb[0][0]); rA = __fdividef(1.f, MA); cA = __logf(MA);
        MB = blockmax4(redb[1][0]); rB = __fdividef(1.f, MB); cB = __logf(MB);

        float uA[4], uB[4];
        #pragma unroll
        for (int kk = 0; kk < 4; kk++){
            int k = 1 + kk;
            uA[kk] = (k == KA) ? 1.f
                   : ((k < KA && ok) ? __expf(__ldg(lgpA + (size_t)(lA - 1 - k) * NUM_ + jt)) : 0.f);
            uB[kk] = (k == KB) ? 1.f
                   : ((k < KB && ok) ? __expf(__ldg(lgpB + (size_t)(lB - 1 - k) * NUM_ + jt)) : 0.f);
        }
        const int KMax = (KA > KB) ? KA : KB;
        int k0 = 1;
        while (k0 + 3 <= KMax){
            float nA[4], nB[4];
            #pragma unroll
            for (int kk = 0; kk < 4; kk++){
                int kp = k0 + 4 + kk;
                nA[kk] = (kp < KA && ok) ? __ldg(lgpA + (size_t)(lA - 1 - kp) * NUM_ + jt) : -1.0e30f;
                nB[kk] = (kp < KB && ok) ? __ldg(lgpB + (size_t)(lB - 1 - kp) * NUM_ + jt) : -1.0e30f;
            }
            #pragma unroll
            for (int kk = 0; kk < 4; kk++){
                const int k = k0 + kk;
                const bool aAct = (k <= KA), bAct = (k <= KB);
                if (aAct & bAct){
                    float sA, sB;
                    dot128x2(pbw[0][(k & 1) ^ 1], pbw[1][(k & 1) ^ 1], E, sA, sB);
                    float vA = sA * rA * uA[kk];
                    float vB = sB * rB * uB[kk];
                    float MwA = redux_max_pos(vA);
                    float MwB = redux_max_pos(vB);
                    if (lane == 0){ redb[0][k & 1][wp] = MwA; redb[1][k & 1][wp] = MwB; }
                    pbw[0][k & 1][jt] = vA;
                    pbw[1][k & 1][jt] = vB;
                } else if (aAct){
                    float vA = dot128(pbw[0][(k & 1) ^ 1], E) * rA * uA[kk];
                    float MwA = redux_max_pos(vA);
                    if (lane == 0) redb[0][k & 1][wp] = MwA;
                    pbw[0][k & 1][jt] = vA;
                } else if (bAct){
                    float vB = dot128(pbw[1][(k & 1) ^ 1], E) * rB * uB[kk];
                    float MwB = redux_max_pos(vB);
                    if (lane == 0) redb[1][k & 1][wp] = MwB;
                    pbw[1][k & 1][jt] = vB;
                }
                GBAR(2);
                if (aAct){ MA = blockmax4(redb[0][k & 1]); rA = __fdividef(1.f, MA); cA += __logf(MA); }
                if (bAct){ MB = blockmax4(redb[1][k & 1]); rB = __fdividef(1.f, MB); cB += __logf(MB); }
            }
            #pragma unroll
            for (int kk = 0; kk < 4; kk++){
                int kn = k0 + 4 + kk;
                uA[kk] = (kn == KA) ? 1.f : __expf(nA[kk]);
                uB[kk] = (kn == KB) ? 1.f : __expf(nB[kk]);
            }
            k0 += 4;
        }
        #pragma unroll
        for (int kk = 0; kk < 3; kk++){
            const int k = k0 + kk;
            if (k <= KMax){
                const bool aAct = (k <= KA), bAct = (k <= KB);
                if (aAct){
                    float vA = dot128(pbw[0][(k & 1) ^ 1], E) * rA * uA[kk];
                    float MwA = redux_max_pos(vA);
                    if (lane == 0) redb[0][k & 1][wp] = MwA;
                    pbw[0][k & 1][jt] = vA;
                }
                if (bAct){
                    float vB = dot128(pbw[1][(k & 1) ^ 1], E) * rB * uB[kk];
                    float MwB = redux_max_pos(vB);
                    if (lane == 0) redb[1][k & 1][wp] = MwB;
                    pbw[1][k & 1][jt] = vB;
                }
                GBAR(2);
                if (aAct){ MA = blockmax4(redb[0][k & 1]); rA = __fdividef(1.f, MA); cA += __logf(MA); }
                if (bAct){ MB = blockmax4(redb[1][k & 1]); rB = __fdividef(1.f, MB); cB += __logf(MB); }
            }
        }
        if (jt == 0){ scal[0][1] = cA - __logf(MA); scal[1][1] = cB - __logf(MB); }
    }

    // =============== merge: norm_X = log(sum_j a_X[j]*b_X[j]) + scal_Xf + scal_Xb ===============
    __syncthreads();
    {
        const int sx = grp;                       // group g finalizes seq g
        const int lX = sx ? lB : lA;
        const int mX = lX >> 1, KX = lX - mX;
        const float* af = pf [sx][mX & 1];
        const float* ab = pbw[sx][KX & 1];
        float prod = af[jt] * ab[jt];
        #pragma unroll
        for (int o = 16; o; o >>= 1){
            prod  += __shfl_xor_sync(0xffffffffu, prod,  o);
            gpart += __shfl_xor_sync(0xffffffffu, gpart, o);
        }
        if (lane == 0){ redS[sx][wp] = prod; redG[sx][wp] = gpart; }
        __syncthreads();
        if (jt == 0){
            float S = redS[sx][0] + redS[sx][1] + redS[sx][2] + redS[sx][3];
            float G = redG[sx][0] + redG[sx][1] + redG[sx][2] + redG[sx][3];
            int seqX = sx ? seqB : seqA;
            out[seqX] = G - (__logf(S) + scal[sx][0] + scal[sx][1]);
        }
    }
}

extern "C" void kernel_launch(void* const* d_in, const int* in_sizes, int n_in,
                              void* d_out, int out_size)
{
    (void)in_sizes; (void)n_in; (void)out_size;
    const float* logits = (const float*)d_in[0];
    const int*   labels = (const int*)d_in[1];
    const int*   lens   = (const int*)d_in[2];
    const float* trans  = (const float*)d_in[3];
    float*       out    = (float*)d_out;

    crf_sort_kernel<<<1, B_>>>(lens);
    crf_main_kernel<<<B_ / 2, 256>>>(logits, labels, lens, trans, out);
}

// round 14
// speedup vs baseline: 1.8812x; 1.8812x over previous
#include <cuda_runtime.h>

#define B_    256
#define T_    1024
#define NUM_  126
#define L_    128

__device__ int d_perm[B_];

// Rank-sort sequences by length (descending), deterministic, O(n^2) with n=256.
__global__ void crf_sort_kernel(const int* __restrict__ lens){
    __shared__ int sl[B_];
    int i = threadIdx.x;
    sl[i] = lens[i];
    __syncthreads();
    int v = sl[i];
    int r = 0;
    #pragma unroll 8
    for (int j = 0; j < B_; j++){
        int w = sl[j];
        r += (int)((w > v) | ((w == v) & (j < i)));
    }
    d_perm[r] = i;
}

__device__ __forceinline__ void ffma2(unsigned long long &d, unsigned long long a, unsigned long long b){
    asm volatile("fma.rn.f32x2 %0, %1, %2, %0;" : "+l"(d) : "l"(a), "l"(b));
}
__device__ __forceinline__ unsigned long long fadd2(unsigned long long a, unsigned long long b){
    unsigned long long d;
    asm volatile("add.rn.f32x2 %0, %1, %2;" : "=l"(d) : "l"(a), "l"(b));
    return d;
}
// Warp max of a NON-NEGATIVE float (bits are s32-monotonic).
__device__ __forceinline__ float redux_max_pos(float v){
    int r;
    asm volatile("redux.sync.max.s32 %0, %1, 0xffffffff;" : "=r"(r) : "r"(__float_as_int(v)));
    return __int_as_float(r);
}
__device__ __forceinline__ float blockmax4(const float* red){
    float4 rv = *(const float4*)red;
    return fmaxf(fmaxf(rv.x, rv.y), fmaxf(rv.z, rv.w));
}

// Full dot: s = sum_{i<128} E[i]*p[i]; E = 64 packed f32x2 regs; p pure broadcast.
__device__ __forceinline__ float dot128(const float* __restrict__ p, const unsigned long long* __restrict__ E){
    const ulonglong2* pd = (const ulonglong2*)p;
    unsigned long long a0 = 0ull, a1 = 0ull, a2 = 0ull, a3 = 0ull;
    #pragma unroll
    for (int i = 0; i < 32; i += 2){
        ulonglong2 q0 = pd[i];
        ulonglong2 q1 = pd[i + 1];
        ffma2(a0, E[2*i + 0], q0.x);
        ffma2(a1, E[2*i + 1], q0.y);
        ffma2(a2, E[2*i + 2], q1.x);
        ffma2(a3, E[2*i + 3], q1.y);
    }
    unsigned long long s2 = fadd2(fadd2(a0, a1), fadd2(a2, a3));
    return __uint_as_float((unsigned)(s2 & 0xffffffffull)) +
           __uint_as_float((unsigned)(s2 >> 32));
}

#define GBAR(id) asm volatile("bar.sync %0, 128;" :: "r"(id) : "memory")

__global__ void __launch_bounds__(256, 1)
crf_main_kernel(const float* __restrict__ logits,
                const int*   __restrict__ labels,
                const int*   __restrict__ lens,
                const float* __restrict__ trans,
                float*       __restrict__ out)
{
    __shared__ __align__(16) float pbuf_all[2][2][L_];   // [group][parity][label]
    __shared__ __align__(16) float red_all[2][2][4];     // [group][parity][warp]
    __shared__ float scal[2];
    __shared__ float redS[8], redG[8];

    const int tid  = threadIdx.x;
    const int grp  = tid >> 7;        // 0 = forward, 1 = backward
    const int jt   = tid & 127;
    const int lane = tid & 31;
    const int wp   = jt >> 5;
    const int w8   = tid >> 5;

    const int seq = d_perm[blockIdx.x];   // rank = bid (descending length)
    const int len = lens[seq];
    const int m   = len >> 1;             // forward steps
    const int K   = len - m;              // backward matvecs (>=1)

    float (*pb)[L_] = pbuf_all[grp];
    float (*red)[4] = red_all[grp];

    // ---- E regs: fwd = exp(Tr) row jt; bwd = exp(Tr) column jt (transposed matvec) ----
    unsigned long long E[64];
    #pragma unroll
    for (int q = 0; q < 64; q++){
        float e0, e1;
        if (grp == 0){
            e0 = expf(trans[jt * L_ + 2*q]);
            e1 = expf(trans[jt * L_ + 2*q + 1]);
        } else {
            e0 = expf(trans[(2*q    ) * L_ + jt]);
            e1 = expf(trans[(2*q + 1) * L_ + jt]);
        }
        E[q] = (unsigned long long)__float_as_uint(e0)
             | ((unsigned long long)__float_as_uint(e1) << 32);
    }

    const float* lgp = logits + (size_t)seq * T_ * NUM_;

    // ---- gold score partial (256 threads stride over time) ----
    float gpart = 0.f;
    {
        const int* lab = labels + seq * T_;
        for (int t = tid; t < len; t += 256){
            int l1 = lab[t];
            gpart += lgp[(size_t)t * NUM_ + l1];
            int l0 = (t == 0) ? (L_ - 2) : lab[t - 1];
            gpart += trans[l1 * L_ + l0];
        }
        if (tid == 0) gpart += trans[(L_ - 1) * L_ + lab[len - 1]];
    }

    const bool ok = (jt < NUM_);
    float c = 0.f, r = 1.f, Mcur = 1.f;
    float ubuf[4];

    if (grp == 0){
        // ================= FORWARD: a <- u_t * (E a), t = 0..m-1 =================
        pb[0][jt] = (jt == (L_ - 2)) ? 1.f : 0.f;
        GBAR(1);
        #pragma unroll
        for (int k = 0; k < 4; k++)
            ubuf[k] = ok ? __expf(__ldg(lgp + (size_t)k * NUM_ + jt)) : 0.f;

        int t0 = 0;
        while (t0 + 4 <= m){
            float nlg[4];
            #pragma unroll
            for (int k = 0; k < 4; k++){
                int tp = t0 + 4 + k;
                nlg[k] = (ok && tp < T_) ? __ldg(lgp + (size_t)tp * NUM_ + jt) : -1.0e30f;
            }
            #pragma unroll
            for (int k = 0; k < 4; k++){
                const int t = t0 + k;
                float s = dot128(pb[t & 1], E);
                float v = s * ubuf[k] * r;              // stale renorm scale
                float Mw = redux_max_pos(v);
                if (lane == 0) red[t & 1][wp] = Mw;
                pb[(t & 1) ^ 1][jt] = v;
                GBAR(1);
                Mcur = blockmax4(red[t & 1]);
                r = __fdividef(1.f, Mcur);
                c += __logf(Mcur);
            }
            #pragma unroll
            for (int k = 0; k < 4; k++) ubuf[k] = __expf(nlg[k]);
            t0 += 4;
        }
        #pragma unroll
        for (int k = 0; k < 3; k++){
            const int t = t0 + k;
            if (t < m){
                float s = dot128(pb[t & 1], E);
                float v = s * ubuf[k] * r;
                float Mw = redux_max_pos(v);
                if (lane == 0) red[t & 1][wp] = Mw;
                pb[(t & 1) ^ 1][jt] = v;
                GBAR(1);
                Mcur = blockmax4(red[t & 1]);
                r = __fdividef(1.f, Mcur);
                c += __logf(Mcur);
            }
        }
        if (jt == 0) scal[0] = c - __logf(Mcur);        // m==0: 0
    } else {
        // ================= BACKWARD: b <- E^T (u_t * b), matvecs k = 1..K =================
        // z0 = u_{len-1} * w,  w[j] = exp(Tr[end, j])
        float wj = __expf(trans[(L_ - 1) * L_ + jt]);
        float ul = ok ? __expf(__ldg(lgp + (size_t)(len - 1) * NUM_ + jt)) : 0.f;
        float v0 = ul * wj;
        float Mw0 = redux_max_pos(v0);
        if (lane == 0) red[0][wp] = Mw0;
        pb[0][jt] = v0;
        GBAR(2);
        Mcur = blockmax4(red[0]);
        r = __fdividef(1.f, Mcur);
        c = __logf(Mcur);

        // ubuf[kk] = u for matvec k0+kk; matvec K uses u=1 (no emission on that hop).
        #pragma unroll
        for (int kk = 0; kk < 4; kk++){
            int k = 1 + kk;
            ubuf[kk] = (k == K) ? 1.f
                     : ((k < K && ok) ? __expf(__ldg(lgp + (size_t)(len - 1 - k) * NUM_ + jt)) : 0.f);
        }

        int k0 = 1;
        while (k0 + 3 <= K){
            float nlg[4];
            #pragma unroll
            for (int kk = 0; kk < 4; kk++){
                int kp = k0 + 4 + kk;
                nlg[kk] = (kp < K && ok) ? __ldg(lgp + (size_t)(len - 1 - kp) * NUM_ + jt) : -1.0e30f;
            }
            #pragma unroll
            for (int kk = 0; kk < 4; kk++){
                const int k = k0 + kk;
                float s = dot128(pb[(k & 1) ^ 1], E);   // read parity (k-1)&1
                float v = s * r * ubuf[kk];
                float Mw = redux_max_pos(v);
                if (lane == 0) red[k & 1][wp] = Mw;
                pb[k & 1][jt] = v;
                GBAR(2);
                Mcur = blockmax4(red[k & 1]);
                r = __fdividef(1.f, Mcur);
                c += __logf(Mcur);
            }
            #pragma unroll
            for (int kk = 0; kk < 4; kk++){
                int kn = k0 + 4 + kk;
                ubuf[kk] = (kn == K) ? 1.f : __expf(nlg[kk]);
            }
            k0 += 4;
        }
        #pragma unroll
        for (int kk = 0; kk < 3; kk++){
            const int k = k0 + kk;
            if (k <= K){
                float s = dot128(pb[(k & 1) ^ 1], E);
                float v = s * r * ubuf[kk];
                float Mw = redux_max_pos(v);
                if (lane == 0) red[k & 1][wp] = Mw;
                pb[k & 1][jt] = v;
                GBAR(2);
                Mcur = blockmax4(red[k & 1]);
                r = __fdividef(1.f, Mcur);
                c += __logf(Mcur);
            }
        }
        if (jt == 0) scal[1] = c - __logf(Mcur);
    }

    // ================= merge: norm = log(sum_j a[j]*b[j]) + cf' + cb' =================
    __syncthreads();
    const float* A  = pbuf_all[0][m & 1];
    const float* Bv = pbuf_all[1][K & 1];
    float prod = (tid < L_) ? A[tid] * Bv[tid] : 0.f;
    #pragma unroll
    for (int o = 16; o; o >>= 1){
        prod  += __shfl_xor_sync(0xffffffffu, prod,  o);
        gpart += __shfl_xor_sync(0xffffffffu, gpart, o);
    }
    if (lane == 0){ redS[w8] = prod; redG[w8] = gpart; }
    __syncthreads();
    if (tid == 0){
        float S = 0.f, G = 0.f;
        #pragma unroll
        for (int i = 0; i < 8; i++){ S += redS[i]; G += redG[i]; }
        out[seq] = G - (__logf(S) + scal[0] + scal[1]);
    }
}

extern "C" void kernel_launch(void* const* d_in, const int* in_sizes, int n_in,
                              void* d_out, int out_size)
{
    (void)in_sizes; (void)n_in; (void)out_size;
    const float* logits = (const float*)d_in[0];
    const int*   labels = (const int*)d_in[1];
    const int*   lens   = (const int*)d_in[2];
    const float* trans  = (const float*)d_in[3];
    float*       out    = (float*)d_out;

    crf_sort_kernel<<<1, B_>>>(lens);
    crf_main_kernel<<<B_, 256>>>(logits, labels, lens, trans, out);
}